// round 7
// baseline (speedup 1.0000x reference)
#include <cuda_runtime.h>
#include <cuda_fp16.h>

// Problem constants
#define Bb    4
#define Tt    16
#define Hh    64
#define Ww    64
#define Cc    256
#define NCLS  512
#define TAPS  27
#define WCHUNK 32
#define WOFF_BYTES (TAPS * Cc * 2)   // 13824 bytes per class row-block

// Transposed fp16 weight table: [class][tap][channel]
__device__ __align__(16) __half g_wt[NCLS * TAPS * Cc];

// ---------------------------------------------------------------------------
// Kernel A: transpose + fp16 convert, smem-tiled so both sides are coalesced.
// ---------------------------------------------------------------------------
__global__ void __launch_bounds__(256) wt_transpose_kernel(const float* __restrict__ w)
{
    __shared__ float s[32 * 27];
    const int bx  = blockIdx.x;
    const int n   = bx >> 3;
    const int c0  = (bx & 7) * 32;
    const int tid = threadIdx.x;

    for (int i = tid; i < 32 * 27; i += 256) {
        int cl = i / 27, k = i % 27;
        s[i] = w[(size_t)(c0 + cl) * (NCLS * TAPS) + n * TAPS + k];
    }
    __syncthreads();
    for (int j = tid; j < 32 * 27; j += 256) {
        int k = j >> 5, cl = j & 31;
        g_wt[(n * TAPS + k) * Cc + c0 + cl] = __float2half_rn(s[cl * 27 + k]);
    }
}

// ---------------------------------------------------------------------------
// Kernel B: gather-accumulate, LDG.128.CG + 4-tap fp16 tree.
// R7 change vs R6: gather loads use __ldcg (L2-cached, NO L1 allocation).
// Rationale: 4 variants all pinned at ~200us with L1~77%/L2~73%; the gather
// working set (13.8MB) never hits in L1, so every missed byte was charged
// TWICE in l1tex wavefronts (fill + read-return). .cg removes the fill.
// ---------------------------------------------------------------------------
__global__ void __launch_bounds__(256, 5) onehot_conv_kernel(
    const int*   __restrict__ indices,
    const float* __restrict__ bias,
    float*       __restrict__ out)
{
    __shared__ __align__(16) float4 s_stage[WCHUNK * 64];   // [w][quad], swizzled, 32KB
    __shared__ int s_off[9 * 34];                           // class byte-offsets, halo'd in w

    const int bx   = blockIdx.x;
    const int wblk = bx & 1;
    const int h    = (bx >> 1) & 63;
    const int t    = (bx >> 7) & 15;
    const int b    = bx >> 11;
    const int w0   = wblk * WCHUNK;
    const int tid  = threadIdx.x;

    // Halo of class byte-offsets: 9 (dt,dh) rows x 34 w, edge-clamped.
    for (int i = tid; i < 9 * 34; i += 256) {
        int r  = i / 34, j = i % 34;
        int dt = r / 3,  dh = r % 3;
        int st = t + dt - 2; if (st < 0) st = 0;
        int sh = h + dh - 1; if (sh < 0) sh = 0; if (sh > Hh - 1) sh = Hh - 1;
        int gw = w0 + j - 1; if (gw < 0) gw = 0; if (gw > Ww - 1) gw = Ww - 1;
        s_off[i] = indices[((b * Tt + st) * Hh + sh) * Ww + gw] * WOFF_BYTES;
    }
    __syncthreads();

    const int warp = tid >> 5;
    const int lane = tid & 31;
    const int kl   = lane < 27 ? lane : 26;     // lane -> tap (guarded)
    const int rIdx = (kl / 3) * 34 + (kl % 3);  // row part of s_off index

    const char* wtb  = reinterpret_cast<const char*>(g_wt);
    const char* base = wtb + lane * 16;          // this lane's 8 channels (fp16 x8 = 16B)

    const float4 bz0 = *reinterpret_cast<const float4*>(bias + 8 * lane);
    const float4 bz1 = *reinterpret_cast<const float4*>(bias + 8 * lane + 4);

    #pragma unroll 1
    for (int p = 0; p < 4; p++) {
        const int w_l = p * 8 + warp;
        // each lane holds the class byte-offset for tap `lane` at this position
        const int myoff = s_off[rIdx + w_l];

        float4 a0 = bz0, a1 = bz1;

        // 6 groups of 4 taps: fp16 quad-tree, one fp32 add per group.
        #pragma unroll
        for (int g = 0; g < 6; g++) {
            const int k  = g * 4;
            const int o0 = __shfl_sync(0xffffffffu, myoff, k);
            const int o1 = __shfl_sync(0xffffffffu, myoff, k + 1);
            const int o2 = __shfl_sync(0xffffffffu, myoff, k + 2);
            const int o3 = __shfl_sync(0xffffffffu, myoff, k + 3);
            uint4 u0 = __ldcg(reinterpret_cast<const uint4*>(base + o0 + (k + 0) * 512));
            uint4 u1 = __ldcg(reinterpret_cast<const uint4*>(base + o1 + (k + 1) * 512));
            uint4 u2 = __ldcg(reinterpret_cast<const uint4*>(base + o2 + (k + 2) * 512));
            uint4 u3 = __ldcg(reinterpret_cast<const uint4*>(base + o3 + (k + 3) * 512));
            __half2 sx = __hadd2(__hadd2(*reinterpret_cast<__half2*>(&u0.x), *reinterpret_cast<__half2*>(&u1.x)),
                                 __hadd2(*reinterpret_cast<__half2*>(&u2.x), *reinterpret_cast<__half2*>(&u3.x)));
            __half2 sy = __hadd2(__hadd2(*reinterpret_cast<__half2*>(&u0.y), *reinterpret_cast<__half2*>(&u1.y)),
                                 __hadd2(*reinterpret_cast<__half2*>(&u2.y), *reinterpret_cast<__half2*>(&u3.y)));
            __half2 sz = __hadd2(__hadd2(*reinterpret_cast<__half2*>(&u0.z), *reinterpret_cast<__half2*>(&u1.z)),
                                 __hadd2(*reinterpret_cast<__half2*>(&u2.z), *reinterpret_cast<__half2*>(&u3.z)));
            __half2 sw2 = __hadd2(__hadd2(*reinterpret_cast<__half2*>(&u0.w), *reinterpret_cast<__half2*>(&u1.w)),
                                  __hadd2(*reinterpret_cast<__half2*>(&u2.w), *reinterpret_cast<__half2*>(&u3.w)));
            float2 f;
            f = __half22float2(sx);  a0.x += f.x; a0.y += f.y;
            f = __half22float2(sy);  a0.z += f.x; a0.w += f.y;
            f = __half22float2(sz);  a1.x += f.x; a1.y += f.y;
            f = __half22float2(sw2); a1.z += f.x; a1.w += f.y;
        }
        {   // taps 24,25,26: 3-tap fp16 tree
            const int o0 = __shfl_sync(0xffffffffu, myoff, 24);
            const int o1 = __shfl_sync(0xffffffffu, myoff, 25);
            const int o2 = __shfl_sync(0xffffffffu, myoff, 26);
            uint4 u0 = __ldcg(reinterpret_cast<const uint4*>(base + o0 + 24 * 512));
            uint4 u1 = __ldcg(reinterpret_cast<const uint4*>(base + o1 + 25 * 512));
            uint4 u2 = __ldcg(reinterpret_cast<const uint4*>(base + o2 + 26 * 512));
            __half2 sx = __hadd2(__hadd2(*reinterpret_cast<__half2*>(&u0.x), *reinterpret_cast<__half2*>(&u1.x)),
                                 *reinterpret_cast<__half2*>(&u2.x));
            __half2 sy = __hadd2(__hadd2(*reinterpret_cast<__half2*>(&u0.y), *reinterpret_cast<__half2*>(&u1.y)),
                                 *reinterpret_cast<__half2*>(&u2.y));
            __half2 sz = __hadd2(__hadd2(*reinterpret_cast<__half2*>(&u0.z), *reinterpret_cast<__half2*>(&u1.z)),
                                 *reinterpret_cast<__half2*>(&u2.z));
            __half2 sw2 = __hadd2(__hadd2(*reinterpret_cast<__half2*>(&u0.w), *reinterpret_cast<__half2*>(&u1.w)),
                                  *reinterpret_cast<__half2*>(&u2.w));
            float2 f;
            f = __half22float2(sx);  a0.x += f.x; a0.y += f.y;
            f = __half22float2(sy);  a0.z += f.x; a0.w += f.y;
            f = __half22float2(sz);  a1.x += f.x; a1.y += f.y;
            f = __half22float2(sw2); a1.z += f.x; a1.w += f.y;
        }

        // Lane l holds logical quads 2l (a0) and 2l+1 (a1).
        // Permute: quad 2l -> col l, quad 2l+1 -> col 32+l, XOR-swizzled by w.
        const int sw = w_l & 31;
        s_stage[w_l * 64 + (lane ^ sw)]        = a0;
        s_stage[w_l * 64 + 32 + (lane ^ sw)]   = a1;
    }
    __syncthreads();

    // Read-back: logical quad qq = 2l+e lives at phys col e*32 + l.
    const size_t THW   = (size_t)Tt * Hh * Ww;
    const size_t obase = (size_t)b * Cc * THW + (size_t)t * (Hh * Ww) + (size_t)h * Ww + w0;
    #pragma unroll
    for (int qq = warp; qq < 64; qq += 8) {
        const int pcol = ((qq & 1) << 5) | (qq >> 1);
        float4 v = s_stage[lane * 64 + (pcol ^ (lane & 31))];
        const int c = qq * 4;
        out[obase + (size_t)(c + 0) * THW + lane] = v.x;
        out[obase + (size_t)(c + 1) * THW + lane] = v.y;
        out[obase + (size_t)(c + 2) * THW + lane] = v.z;
        out[obase + (size_t)(c + 3) * THW + lane] = v.w;
    }
}

// ---------------------------------------------------------------------------
extern "C" void kernel_launch(void* const* d_in, const int* in_sizes, int n_in,
                              void* d_out, int out_size)
{
    const int*   indices = (const int*)  d_in[0];
    const float* weight  = (const float*)d_in[1];
    const float* bias    = (const float*)d_in[2];
    float*       out     = (float*)d_out;

    wt_transpose_kernel<<<NCLS * (Cc / 32), 256>>>(weight);

    const int grid = Bb * Tt * Hh * (Ww / WCHUNK);   // 8192
    onehot_conv_kernel<<<grid, 256>>>(indices, bias, out);
}

// round 8
// speedup vs baseline: 1.0924x; 1.0924x over previous
#include <cuda_runtime.h>
#include <cuda_fp16.h>

// Problem constants
#define Bb    4
#define Tt    16
#define Hh    64
#define Ww    64
#define Cc    256
#define NCLS  512
#define TAPS  27
#define WCHUNK 32
#define WOFF_BYTES  (TAPS * Cc * 2)   // 13824 B per class in main table
#define CWOFF_BYTES (9 * Cc * 2)      // 4608 B per class in combined tables

// Transposed fp16 weight table: [class][tap][channel]
__device__ __align__(16) __half g_wt[NCLS * TAPS * Cc];
// Temporal-edge combined tables: [class][dh*3+dw][channel]
//   g_wc01  = W(dt=0)+W(dt=1)      (for t==1, clamped cell t'=0)
//   g_wc012 = W(dt=0)+W(dt=1)+W(dt=2)  (for t==0)
__device__ __align__(16) __half g_wc01 [NCLS * 9 * Cc];
__device__ __align__(16) __half g_wc012[NCLS * 9 * Cc];

// ---------------------------------------------------------------------------
// Kernel A: transpose + fp16 convert + edge-combined tables.
// ---------------------------------------------------------------------------
__global__ void __launch_bounds__(256) wt_transpose_kernel(const float* __restrict__ w)
{
    __shared__ float s[32 * 27];     // [c_local][k], stride 27 -> conflict-free
    const int bx  = blockIdx.x;
    const int n   = bx >> 3;
    const int c0  = (bx & 7) * 32;
    const int tid = threadIdx.x;

    for (int i = tid; i < 32 * 27; i += 256) {
        int cl = i / 27, k = i % 27;
        s[i] = w[(size_t)(c0 + cl) * (NCLS * TAPS) + n * TAPS + k];
    }
    __syncthreads();
    for (int j = tid; j < 32 * 27; j += 256) {
        int k = j >> 5, cl = j & 31;
        g_wt[(n * TAPS + k) * Cc + c0 + cl] = __float2half_rn(s[cl * 27 + k]);
    }
    // Combined temporal-edge taps (fp32 sum, single fp16 rounding).
    for (int j = tid; j < 32 * 9; j += 256) {
        int jt = j >> 5, cl = j & 31;          // jt = dh*3+dw
        float w0 = s[cl * 27 + jt];            // dt=0
        float w1 = s[cl * 27 + 9 + jt];        // dt=1
        float w2 = s[cl * 27 + 18 + jt];       // dt=2
        g_wc01 [(n * 9 + jt) * Cc + c0 + cl] = __float2half_rn(w0 + w1);
        g_wc012[(n * 9 + jt) * Cc + c0 + cl] = __float2half_rn(w0 + w1 + w2);
    }
}

// ---------------------------------------------------------------------------
// Kernel B: gather-accumulate (R5 config: LDG.128, pairwise HADD2).
// New: t==0 blocks use g_wc012 (9 gathers), t==1 use g_wc01 + dt=2 rows
// (18 gathers) — deletes 6.25% of the irreducible gather traffic.
// ---------------------------------------------------------------------------
__global__ void __launch_bounds__(256, 5) onehot_conv_kernel(
    const int*   __restrict__ indices,
    const float* __restrict__ bias,
    float*       __restrict__ out)
{
    __shared__ __align__(16) float4 s_stage[WCHUNK * 64];   // [w][quad], swizzled, 32KB
    __shared__ int s_off[9 * 34];                           // raw classes, halo'd in w

    const int bx   = blockIdx.x;
    const int wblk = bx & 1;
    const int h    = (bx >> 1) & 63;
    const int t    = (bx >> 7) & 15;
    const int b    = bx >> 11;
    const int w0   = wblk * WCHUNK;
    const int tid  = threadIdx.x;

    // Halo of classes: 9 (dt,dh) rows x 34 w, edge-clamped.
    for (int i = tid; i < 9 * 34; i += 256) {
        int r  = i / 34, j = i % 34;
        int dt = r / 3,  dh = r % 3;
        int st = t + dt - 2; if (st < 0) st = 0;
        int sh = h + dh - 1; if (sh < 0) sh = 0; if (sh > Hh - 1) sh = Hh - 1;
        int gw = w0 + j - 1; if (gw < 0) gw = 0; if (gw > Ww - 1) gw = Ww - 1;
        s_off[i] = indices[((b * Tt + st) * Hh + sh) * Ww + gw];
    }
    __syncthreads();

    const int warp = tid >> 5;
    const int lane = tid & 31;
    const int kl   = lane < 27 ? lane : 26;     // lane -> tap (guarded)
    const int rIdx = (kl / 3) * 34 + (kl % 3);  // row part of s_off index

    const char* baseW  = reinterpret_cast<const char*>(g_wt)    + lane * 16; // 8 ch, fp16x8
    const char* baseC1 = reinterpret_cast<const char*>(g_wc01)  + lane * 16;
    const char* baseC2 = reinterpret_cast<const char*>(g_wc012) + lane * 16;

    const float4 bz0 = *reinterpret_cast<const float4*>(bias + 8 * lane);
    const float4 bz1 = *reinterpret_cast<const float4*>(bias + 8 * lane + 4);

    #pragma unroll 1
    for (int p = 0; p < 4; p++) {
        const int w_l = p * 8 + warp;
        const int cls = s_off[rIdx + w_l];      // this lane's tap-class
        const int moW = cls * WOFF_BYTES;       // offset into g_wt
        const int moC = cls * CWOFF_BYTES;      // offset into combined tables

        float4 a0 = bz0, a1 = bz1;

        if (t >= 2) {
            // 13 pairs + 1 single from the full table.
            #pragma unroll
            for (int k = 0; k < 26; k += 2) {
                const int o0 = __shfl_sync(0xffffffffu, moW, k);
                const int o1 = __shfl_sync(0xffffffffu, moW, k + 1);
                uint4 u0 = *reinterpret_cast<const uint4*>(baseW + o0 + k * 512);
                uint4 u1 = *reinterpret_cast<const uint4*>(baseW + o1 + (k + 1) * 512);
                __half2 s0 = __hadd2(*reinterpret_cast<__half2*>(&u0.x), *reinterpret_cast<__half2*>(&u1.x));
                __half2 s1 = __hadd2(*reinterpret_cast<__half2*>(&u0.y), *reinterpret_cast<__half2*>(&u1.y));
                __half2 s2 = __hadd2(*reinterpret_cast<__half2*>(&u0.z), *reinterpret_cast<__half2*>(&u1.z));
                __half2 s3 = __hadd2(*reinterpret_cast<__half2*>(&u0.w), *reinterpret_cast<__half2*>(&u1.w));
                float2 f;
                f = __half22float2(s0); a0.x += f.x; a0.y += f.y;
                f = __half22float2(s1); a0.z += f.x; a0.w += f.y;
                f = __half22float2(s2); a1.x += f.x; a1.y += f.y;
                f = __half22float2(s3); a1.z += f.x; a1.w += f.y;
            }
            const int o = __shfl_sync(0xffffffffu, moW, 26);
            uint4 u = *reinterpret_cast<const uint4*>(baseW + o + 26 * 512);
            float2 f;
            f = __half22float2(*reinterpret_cast<__half2*>(&u.x)); a0.x += f.x; a0.y += f.y;
            f = __half22float2(*reinterpret_cast<__half2*>(&u.y)); a0.z += f.x; a0.w += f.y;
            f = __half22float2(*reinterpret_cast<__half2*>(&u.z)); a1.x += f.x; a1.y += f.y;
            f = __half22float2(*reinterpret_cast<__half2*>(&u.w)); a1.z += f.x; a1.w += f.y;
        } else if (t == 1) {
            // 9 pairs: (Wc01 row j from dt=0 cells) + (W row 18+j from dt=2 cells).
            #pragma unroll
            for (int j = 0; j < 9; j++) {
                const int oc = __shfl_sync(0xffffffffu, moC, j);        // lanes 0..8: dt=0 cells
                const int ow = __shfl_sync(0xffffffffu, moW, 18 + j);   // lanes 18..26: dt=2 cells
                uint4 u0 = *reinterpret_cast<const uint4*>(baseC1 + oc + j * 512);
                uint4 u1 = *reinterpret_cast<const uint4*>(baseW + ow + (18 + j) * 512);
                __half2 s0 = __hadd2(*reinterpret_cast<__half2*>(&u0.x), *reinterpret_cast<__half2*>(&u1.x));
                __half2 s1 = __hadd2(*reinterpret_cast<__half2*>(&u0.y), *reinterpret_cast<__half2*>(&u1.y));
                __half2 s2 = __hadd2(*reinterpret_cast<__half2*>(&u0.z), *reinterpret_cast<__half2*>(&u1.z));
                __half2 s3 = __hadd2(*reinterpret_cast<__half2*>(&u0.w), *reinterpret_cast<__half2*>(&u1.w));
                float2 f;
                f = __half22float2(s0); a0.x += f.x; a0.y += f.y;
                f = __half22float2(s1); a0.z += f.x; a0.w += f.y;
                f = __half22float2(s2); a1.x += f.x; a1.y += f.y;
                f = __half22float2(s3); a1.z += f.x; a1.w += f.y;
            }
        } else {
            // t == 0: 9 gathers from Wc012 (4 pairs + 1 single).
            #pragma unroll
            for (int j = 0; j < 8; j += 2) {
                const int o0 = __shfl_sync(0xffffffffu, moC, j);
                const int o1 = __shfl_sync(0xffffffffu, moC, j + 1);
                uint4 u0 = *reinterpret_cast<const uint4*>(baseC2 + o0 + j * 512);
                uint4 u1 = *reinterpret_cast<const uint4*>(baseC2 + o1 + (j + 1) * 512);
                __half2 s0 = __hadd2(*reinterpret_cast<__half2*>(&u0.x), *reinterpret_cast<__half2*>(&u1.x));
                __half2 s1 = __hadd2(*reinterpret_cast<__half2*>(&u0.y), *reinterpret_cast<__half2*>(&u1.y));
                __half2 s2 = __hadd2(*reinterpret_cast<__half2*>(&u0.z), *reinterpret_cast<__half2*>(&u1.z));
                __half2 s3 = __hadd2(*reinterpret_cast<__half2*>(&u0.w), *reinterpret_cast<__half2*>(&u1.w));
                float2 f;
                f = __half22float2(s0); a0.x += f.x; a0.y += f.y;
                f = __half22float2(s1); a0.z += f.x; a0.w += f.y;
                f = __half22float2(s2); a1.x += f.x; a1.y += f.y;
                f = __half22float2(s3); a1.z += f.x; a1.w += f.y;
            }
            const int o = __shfl_sync(0xffffffffu, moC, 8);
            uint4 u = *reinterpret_cast<const uint4*>(baseC2 + o + 8 * 512);
            float2 f;
            f = __half22float2(*reinterpret_cast<__half2*>(&u.x)); a0.x += f.x; a0.y += f.y;
            f = __half22float2(*reinterpret_cast<__half2*>(&u.y)); a0.z += f.x; a0.w += f.y;
            f = __half22float2(*reinterpret_cast<__half2*>(&u.z)); a1.x += f.x; a1.y += f.y;
            f = __half22float2(*reinterpret_cast<__half2*>(&u.w)); a1.z += f.x; a1.w += f.y;
        }

        // Lane l holds logical quads 2l (a0) and 2l+1 (a1).
        // Permute: quad 2l -> col l, quad 2l+1 -> col 32+l, XOR-swizzled by w.
        const int sw = w_l & 31;
        s_stage[w_l * 64 + (lane ^ sw)]        = a0;
        s_stage[w_l * 64 + 32 + (lane ^ sw)]   = a1;
    }
    __syncthreads();

    // Read-back: logical quad qq = 2l+e lives at phys col e*32 + l.
    const size_t THW   = (size_t)Tt * Hh * Ww;
    const size_t obase = (size_t)b * Cc * THW + (size_t)t * (Hh * Ww) + (size_t)h * Ww + w0;
    #pragma unroll
    for (int qq = warp; qq < 64; qq += 8) {
        const int pcol = ((qq & 1) << 5) | (qq >> 1);
        float4 v = s_stage[lane * 64 + (pcol ^ (lane & 31))];
        const int c = qq * 4;
        out[obase + (size_t)(c + 0) * THW + lane] = v.x;
        out[obase + (size_t)(c + 1) * THW + lane] = v.y;
        out[obase + (size_t)(c + 2) * THW + lane] = v.z;
        out[obase + (size_t)(c + 3) * THW + lane] = v.w;
    }
}

// ---------------------------------------------------------------------------
extern "C" void kernel_launch(void* const* d_in, const int* in_sizes, int n_in,
                              void* d_out, int out_size)
{
    const int*   indices = (const int*)  d_in[0];
    const float* weight  = (const float*)d_in[1];
    const float* bias    = (const float*)d_in[2];
    float*       out     = (float*)d_out;

    wt_transpose_kernel<<<NCLS * (Cc / 32), 256>>>(weight);

    const int grid = Bb * Tt * Hh * (Ww / WCHUNK);   // 8192
    onehot_conv_kernel<<<grid, 256>>>(indices, bias, out);
}

// round 9
// speedup vs baseline: 1.1579x; 1.0599x over previous
#include <cuda_runtime.h>
#include <cuda_fp16.h>

// Problem constants
#define Bb    4
#define Tt    16
#define Hh    64
#define Ww    64
#define Cc    256
#define NCLS  512
#define TAPS  27
#define WCHUNK 32
#define WOFF_BYTES  (TAPS * Cc * 2)   // 13824 B per class in main table
#define CWOFF_BYTES (9 * Cc * 2)      // 4608 B per class in combined tables

// Transposed fp16 weight table: [class][tap][channel]
__device__ __align__(16) __half g_wt[NCLS * TAPS * Cc];
// Temporal-edge combined tables: [class][dh*3+dw][channel]
//   g_wc01  = W(dt=0)+W(dt=1)          (for t==1, clamped cell t'=0)
//   g_wc012 = W(dt=0)+W(dt=1)+W(dt=2)  (for t==0)
__device__ __align__(16) __half g_wc01 [NCLS * 9 * Cc];
__device__ __align__(16) __half g_wc012[NCLS * 9 * Cc];

// ---------------------------------------------------------------------------
// Kernel A: transpose + fp16 convert + edge-combined tables.
// ---------------------------------------------------------------------------
__global__ void __launch_bounds__(256) wt_transpose_kernel(const float* __restrict__ w)
{
    __shared__ float s[32 * 27];     // [c_local][k], stride 27 -> conflict-free
    const int bx  = blockIdx.x;
    const int n   = bx >> 3;
    const int c0  = (bx & 7) * 32;
    const int tid = threadIdx.x;

    for (int i = tid; i < 32 * 27; i += 256) {
        int cl = i / 27, k = i % 27;
        s[i] = w[(size_t)(c0 + cl) * (NCLS * TAPS) + n * TAPS + k];
    }
    __syncthreads();
    for (int j = tid; j < 32 * 27; j += 256) {
        int k = j >> 5, cl = j & 31;
        g_wt[(n * TAPS + k) * Cc + c0 + cl] = __float2half_rn(s[cl * 27 + k]);
    }
    // Combined temporal-edge taps (fp32 sum, single fp16 rounding).
    for (int j = tid; j < 32 * 9; j += 256) {
        int jt = j >> 5, cl = j & 31;          // jt = dh*3+dw
        float w0 = s[cl * 27 + jt];            // dt=0
        float w1 = s[cl * 27 + 9 + jt];        // dt=1
        float w2 = s[cl * 27 + 18 + jt];       // dt=2
        g_wc01 [(n * 9 + jt) * Cc + c0 + cl] = __float2half_rn(w0 + w1);
        g_wc012[(n * 9 + jt) * Cc + c0 + cl] = __float2half_rn(w0 + w1 + w2);
    }
}

// ---------------------------------------------------------------------------
// Kernel B: gather-accumulate (R8 + fp16 output staging).
// R9 change: the smem stage holds fp16 (16B/lane/position instead of 32B),
// halving STS and LDS wavefronts (the binding budget is the shared 128B/cyc
// l1tex path: gathers 108 wf/pos + STS/LDS/STG; this deletes 8 wf/pos).
// Swizzle: 16B unit u at phys u^(w&31); conflict-free both directions.
// ---------------------------------------------------------------------------
__global__ void __launch_bounds__(256, 5) onehot_conv_kernel(
    const int*   __restrict__ indices,
    const float* __restrict__ bias,
    float*       __restrict__ out)
{
    // [w][32 x 16B units]; each unit = 8 channels in fp16. 16KB.
    __shared__ __align__(16) uint4 s_stage[WCHUNK * 32];
    __shared__ int s_off[9 * 34];                 // raw classes, halo'd in w

    const int bx   = blockIdx.x;
    const int wblk = bx & 1;
    const int h    = (bx >> 1) & 63;
    const int t    = (bx >> 7) & 15;
    const int b    = bx >> 11;
    const int w0   = wblk * WCHUNK;
    const int tid  = threadIdx.x;

    // Halo of classes: 9 (dt,dh) rows x 34 w, edge-clamped.
    for (int i = tid; i < 9 * 34; i += 256) {
        int r  = i / 34, j = i % 34;
        int dt = r / 3,  dh = r % 3;
        int st = t + dt - 2; if (st < 0) st = 0;
        int sh = h + dh - 1; if (sh < 0) sh = 0; if (sh > Hh - 1) sh = Hh - 1;
        int gw = w0 + j - 1; if (gw < 0) gw = 0; if (gw > Ww - 1) gw = Ww - 1;
        s_off[i] = indices[((b * Tt + st) * Hh + sh) * Ww + gw];
    }
    __syncthreads();

    const int warp = tid >> 5;
    const int lane = tid & 31;
    const int kl   = lane < 27 ? lane : 26;     // lane -> tap (guarded)
    const int rIdx = (kl / 3) * 34 + (kl % 3);  // row part of s_off index

    const char* baseW  = reinterpret_cast<const char*>(g_wt)    + lane * 16; // 8 ch, fp16x8
    const char* baseC1 = reinterpret_cast<const char*>(g_wc01)  + lane * 16;
    const char* baseC2 = reinterpret_cast<const char*>(g_wc012) + lane * 16;

    const float4 bz0 = *reinterpret_cast<const float4*>(bias + 8 * lane);
    const float4 bz1 = *reinterpret_cast<const float4*>(bias + 8 * lane + 4);

    #pragma unroll 1
    for (int p = 0; p < 4; p++) {
        const int w_l = p * 8 + warp;
        const int cls = s_off[rIdx + w_l];      // this lane's tap-class
        const int moW = cls * WOFF_BYTES;       // offset into g_wt
        const int moC = cls * CWOFF_BYTES;      // offset into combined tables

        float4 a0 = bz0, a1 = bz1;

        if (t >= 2) {
            // 13 pairs + 1 single from the full table.
            #pragma unroll
            for (int k = 0; k < 26; k += 2) {
                const int o0 = __shfl_sync(0xffffffffu, moW, k);
                const int o1 = __shfl_sync(0xffffffffu, moW, k + 1);
                uint4 u0 = *reinterpret_cast<const uint4*>(baseW + o0 + k * 512);
                uint4 u1 = *reinterpret_cast<const uint4*>(baseW + o1 + (k + 1) * 512);
                __half2 s0 = __hadd2(*reinterpret_cast<__half2*>(&u0.x), *reinterpret_cast<__half2*>(&u1.x));
                __half2 s1 = __hadd2(*reinterpret_cast<__half2*>(&u0.y), *reinterpret_cast<__half2*>(&u1.y));
                __half2 s2 = __hadd2(*reinterpret_cast<__half2*>(&u0.z), *reinterpret_cast<__half2*>(&u1.z));
                __half2 s3 = __hadd2(*reinterpret_cast<__half2*>(&u0.w), *reinterpret_cast<__half2*>(&u1.w));
                float2 f;
                f = __half22float2(s0); a0.x += f.x; a0.y += f.y;
                f = __half22float2(s1); a0.z += f.x; a0.w += f.y;
                f = __half22float2(s2); a1.x += f.x; a1.y += f.y;
                f = __half22float2(s3); a1.z += f.x; a1.w += f.y;
            }
            const int o = __shfl_sync(0xffffffffu, moW, 26);
            uint4 u = *reinterpret_cast<const uint4*>(baseW + o + 26 * 512);
            float2 f;
            f = __half22float2(*reinterpret_cast<__half2*>(&u.x)); a0.x += f.x; a0.y += f.y;
            f = __half22float2(*reinterpret_cast<__half2*>(&u.y)); a0.z += f.x; a0.w += f.y;
            f = __half22float2(*reinterpret_cast<__half2*>(&u.z)); a1.x += f.x; a1.y += f.y;
            f = __half22float2(*reinterpret_cast<__half2*>(&u.w)); a1.z += f.x; a1.w += f.y;
        } else if (t == 1) {
            // 9 pairs: (Wc01 row j, dt=0 cells) + (W row 18+j, dt=2 cells).
            #pragma unroll
            for (int j = 0; j < 9; j++) {
                const int oc = __shfl_sync(0xffffffffu, moC, j);
                const int ow = __shfl_sync(0xffffffffu, moW, 18 + j);
                uint4 u0 = *reinterpret_cast<const uint4*>(baseC1 + oc + j * 512);
                uint4 u1 = *reinterpret_cast<const uint4*>(baseW + ow + (18 + j) * 512);
                __half2 s0 = __hadd2(*reinterpret_cast<__half2*>(&u0.x), *reinterpret_cast<__half2*>(&u1.x));
                __half2 s1 = __hadd2(*reinterpret_cast<__half2*>(&u0.y), *reinterpret_cast<__half2*>(&u1.y));
                __half2 s2 = __hadd2(*reinterpret_cast<__half2*>(&u0.z), *reinterpret_cast<__half2*>(&u1.z));
                __half2 s3 = __hadd2(*reinterpret_cast<__half2*>(&u0.w), *reinterpret_cast<__half2*>(&u1.w));
                float2 f;
                f = __half22float2(s0); a0.x += f.x; a0.y += f.y;
                f = __half22float2(s1); a0.z += f.x; a0.w += f.y;
                f = __half22float2(s2); a1.x += f.x; a1.y += f.y;
                f = __half22float2(s3); a1.z += f.x; a1.w += f.y;
            }
        } else {
            // t == 0: 9 gathers from Wc012 (4 pairs + 1 single).
            #pragma unroll
            for (int j = 0; j < 8; j += 2) {
                const int o0 = __shfl_sync(0xffffffffu, moC, j);
                const int o1 = __shfl_sync(0xffffffffu, moC, j + 1);
                uint4 u0 = *reinterpret_cast<const uint4*>(baseC2 + o0 + j * 512);
                uint4 u1 = *reinterpret_cast<const uint4*>(baseC2 + o1 + (j + 1) * 512);
                __half2 s0 = __hadd2(*reinterpret_cast<__half2*>(&u0.x), *reinterpret_cast<__half2*>(&u1.x));
                __half2 s1 = __hadd2(*reinterpret_cast<__half2*>(&u0.y), *reinterpret_cast<__half2*>(&u1.y));
                __half2 s2 = __hadd2(*reinterpret_cast<__half2*>(&u0.z), *reinterpret_cast<__half2*>(&u1.z));
                __half2 s3 = __hadd2(*reinterpret_cast<__half2*>(&u0.w), *reinterpret_cast<__half2*>(&u1.w));
                float2 f;
                f = __half22float2(s0); a0.x += f.x; a0.y += f.y;
                f = __half22float2(s1); a0.z += f.x; a0.w += f.y;
                f = __half22float2(s2); a1.x += f.x; a1.y += f.y;
                f = __half22float2(s3); a1.z += f.x; a1.w += f.y;
            }
            const int o = __shfl_sync(0xffffffffu, moC, 8);
            uint4 u = *reinterpret_cast<const uint4*>(baseC2 + o + 8 * 512);
            float2 f;
            f = __half22float2(*reinterpret_cast<__half2*>(&u.x)); a0.x += f.x; a0.y += f.y;
            f = __half22float2(*reinterpret_cast<__half2*>(&u.y)); a0.z += f.x; a0.w += f.y;
            f = __half22float2(*reinterpret_cast<__half2*>(&u.z)); a1.x += f.x; a1.y += f.y;
            f = __half22float2(*reinterpret_cast<__half2*>(&u.w)); a1.z += f.x; a1.w += f.y;
        }

        // Pack 8 channels to fp16 and store one 16B unit, XOR-swizzled by w.
        __half2 h0 = __floats2half2_rn(a0.x, a0.y);
        __half2 h1 = __floats2half2_rn(a0.z, a0.w);
        __half2 h2 = __floats2half2_rn(a1.x, a1.y);
        __half2 h3 = __floats2half2_rn(a1.z, a1.w);
        uint4 pk;
        pk.x = *reinterpret_cast<unsigned*>(&h0);
        pk.y = *reinterpret_cast<unsigned*>(&h1);
        pk.z = *reinterpret_cast<unsigned*>(&h2);
        pk.w = *reinterpret_cast<unsigned*>(&h3);
        s_stage[w_l * 32 + (lane ^ (w_l & 31))] = pk;
    }
    __syncthreads();

    // Read-back: logical unit uu (8 channels) at phys uu^(lane&31); lane = w.
    // LDS.128 conflict-free per phase ((uu^l) mod 8 permutes).
    const size_t THW   = (size_t)Tt * Hh * Ww;
    const size_t obase = (size_t)b * Cc * THW + (size_t)t * (Hh * Ww) + (size_t)h * Ww + w0;
    #pragma unroll
    for (int uu = warp; uu < 32; uu += 8) {
        uint4 pk = s_stage[lane * 32 + (uu ^ lane)];
        float2 f0 = __half22float2(*reinterpret_cast<__half2*>(&pk.x));
        float2 f1 = __half22float2(*reinterpret_cast<__half2*>(&pk.y));
        float2 f2 = __half22float2(*reinterpret_cast<__half2*>(&pk.z));
        float2 f3 = __half22float2(*reinterpret_cast<__half2*>(&pk.w));
        const int c = uu * 8;
        out[obase + (size_t)(c + 0) * THW + lane] = f0.x;
        out[obase + (size_t)(c + 1) * THW + lane] = f0.y;
        out[obase + (size_t)(c + 2) * THW + lane] = f1.x;
        out[obase + (size_t)(c + 3) * THW + lane] = f1.y;
        out[obase + (size_t)(c + 4) * THW + lane] = f2.x;
        out[obase + (size_t)(c + 5) * THW + lane] = f2.y;
        out[obase + (size_t)(c + 6) * THW + lane] = f3.x;
        out[obase + (size_t)(c + 7) * THW + lane] = f3.y;
    }
}

// ---------------------------------------------------------------------------
extern "C" void kernel_launch(void* const* d_in, const int* in_sizes, int n_in,
                              void* d_out, int out_size)
{
    const int*   indices = (const int*)  d_in[0];
    const float* weight  = (const float*)d_in[1];
    const float* bias    = (const float*)d_in[2];
    float*       out     = (float*)d_out;

    wt_transpose_kernel<<<NCLS * (Cc / 32), 256>>>(weight);

    const int grid = Bb * Tt * Hh * (Ww / WCHUNK);   // 8192
    onehot_conv_kernel<<<grid, 256>>>(indices, bias, out);
}